// round 2
// baseline (speedup 1.0000x reference)
#include <cuda_runtime.h>

#define N_NODES 100000
#define F_IN    256
#define HID     128
#define CLS     32
#define N_EDGES 1600000

// ---- device scratch (allocation-free rule: static __device__ globals) ----
__device__ __align__(16) float g_h1[N_NODES * HID];     // X @ W1
__device__ __align__(16) float g_a1[N_NODES * HID];     // relu(agg1 + b1)
__device__ __align__(16) float g_h2[N_NODES * CLS];     // a1 @ W2
__device__ int   g_deg[N_NODES];
__device__ float g_dinv[N_NODES];
__device__ int   g_rowptr[N_NODES + 1];
__device__ int   g_cursor[N_NODES];
__device__ int   g_csrc[N_EDGES];

// ---------------- graph preprocessing ----------------
__global__ void k_zero_deg() {
    int i = blockIdx.x * blockDim.x + threadIdx.x;
    if (i < N_NODES) g_deg[i] = 0;
}

__global__ void k_count(const int* __restrict__ ei) {
    int i = blockIdx.x * blockDim.x + threadIdx.x;
    if (i < N_EDGES) {
        int d = ei[N_EDGES + i];
        atomicAdd(&g_deg[d], 1);
    }
}

// single-block exclusive scan of g_deg -> g_rowptr, also fills g_cursor and g_dinv
__global__ void k_scan() {
    __shared__ int warpsum[32];
    __shared__ int carry_s;
    int tid = threadIdx.x, lane = tid & 31, wid = tid >> 5;
    if (tid == 0) carry_s = 0;
    __syncthreads();
    for (int base = 0; base < N_NODES; base += 1024) {
        int i = base + tid;
        int v = (i < N_NODES) ? g_deg[i] : 0;
        int x = v;
        #pragma unroll
        for (int off = 1; off < 32; off <<= 1) {
            int t = __shfl_up_sync(0xffffffffu, x, off);
            if (lane >= off) x += t;
        }
        if (lane == 31) warpsum[wid] = x;
        __syncthreads();
        if (wid == 0) {
            int y = warpsum[lane];
            #pragma unroll
            for (int off = 1; off < 32; off <<= 1) {
                int t = __shfl_up_sync(0xffffffffu, y, off);
                if (lane >= off) y += t;
            }
            warpsum[lane] = y;
        }
        __syncthreads();
        int woff = wid ? warpsum[wid - 1] : 0;
        int incl = x + woff;
        int c = carry_s;
        if (i < N_NODES) {
            int excl = c + incl - v;
            g_rowptr[i] = excl;
            g_cursor[i] = excl;
            g_dinv[i] = (v > 0) ? rsqrtf((float)v) : 0.0f;
        }
        __syncthreads();
        if (tid == 1023) carry_s = c + incl;
        __syncthreads();
    }
    if (threadIdx.x == 0) g_rowptr[N_NODES] = carry_s;
}

__global__ void k_fill(const int* __restrict__ ei) {
    int i = blockIdx.x * blockDim.x + threadIdx.x;
    if (i < N_EDGES) {
        int s = ei[i];
        int d = ei[N_EDGES + i];
        int p = atomicAdd(&g_cursor[d], 1);
        g_csrc[p] = s;
    }
}

// ---------------- GEMM1: h1 = X[100000,256] @ W1[256,128] ----------------
// Block tile 64x128, K-tile 32, 256 threads, each thread 8x4 outputs.
__global__ void k_gemm1(const float* __restrict__ X, const float* __restrict__ W) {
    __shared__ float As[64][32];
    __shared__ float Bs[32][128];
    int tid = threadIdx.x;
    int tx = tid & 31;   // col group (0..31) -> cols tx*4..tx*4+3
    int ty = tid >> 5;   // row group (0..7)  -> rows ty*8..ty*8+7
    int row0 = blockIdx.x * 64;

    float acc[8][4];
    #pragma unroll
    for (int r = 0; r < 8; r++)
        #pragma unroll
        for (int c = 0; c < 4; c++) acc[r][c] = 0.0f;

    for (int k0 = 0; k0 < F_IN; k0 += 32) {
        // load A tile: 64x32 = 512 float4
        #pragma unroll
        for (int l = 0; l < 2; l++) {
            int idx = tid * 2 + l;             // 0..511
            int r = idx >> 3, c4 = idx & 7;
            float4 v = make_float4(0.f, 0.f, 0.f, 0.f);
            int gr = row0 + r;
            if (gr < N_NODES)
                v = *(const float4*)&X[(size_t)gr * F_IN + k0 + c4 * 4];
            *(float4*)&As[r][c4 * 4] = v;
        }
        // load B tile: 32x128 = 1024 float4
        #pragma unroll
        for (int l = 0; l < 4; l++) {
            int idx = tid * 4 + l;             // 0..1023
            int r = idx >> 5, c4 = idx & 31;
            *(float4*)&Bs[r][c4 * 4] = *(const float4*)&W[(k0 + r) * HID + c4 * 4];
        }
        __syncthreads();
        #pragma unroll
        for (int k = 0; k < 32; k++) {
            float4 bv = *(float4*)&Bs[k][tx * 4];
            #pragma unroll
            for (int r = 0; r < 8; r++) {
                float a = As[ty * 8 + r][k];
                acc[r][0] = fmaf(a, bv.x, acc[r][0]);
                acc[r][1] = fmaf(a, bv.y, acc[r][1]);
                acc[r][2] = fmaf(a, bv.z, acc[r][2]);
                acc[r][3] = fmaf(a, bv.w, acc[r][3]);
            }
        }
        __syncthreads();
    }
    #pragma unroll
    for (int r = 0; r < 8; r++) {
        int gr = row0 + ty * 8 + r;
        if (gr < N_NODES)
            *(float4*)&g_h1[(size_t)gr * HID + tx * 4] =
                make_float4(acc[r][0], acc[r][1], acc[r][2], acc[r][3]);
    }
}

// ---------------- agg1: a1 = relu(D^-1/2 A D^-1/2 h1 + b1), warp per node ----------------
__global__ void k_agg1(const float* __restrict__ b1) {
    int w = (blockIdx.x * blockDim.x + threadIdx.x) >> 5;
    int lane = threadIdx.x & 31;
    if (w >= N_NODES) return;
    int s0 = g_rowptr[w], s1 = g_rowptr[w + 1];
    float dd = g_dinv[w];
    float4 acc = make_float4(0.f, 0.f, 0.f, 0.f);
    for (int e = s0; e < s1; e++) {
        int s = g_csrc[e];
        float nrm = g_dinv[s] * dd;
        float4 v = *(const float4*)&g_h1[(size_t)s * HID + lane * 4];
        acc.x = fmaf(nrm, v.x, acc.x);
        acc.y = fmaf(nrm, v.y, acc.y);
        acc.z = fmaf(nrm, v.z, acc.z);
        acc.w = fmaf(nrm, v.w, acc.w);
    }
    float4 bb = *(const float4*)&b1[lane * 4];
    acc.x = fmaxf(acc.x + bb.x, 0.f);
    acc.y = fmaxf(acc.y + bb.y, 0.f);
    acc.z = fmaxf(acc.z + bb.z, 0.f);
    acc.w = fmaxf(acc.w + bb.w, 0.f);
    *(float4*)&g_a1[(size_t)w * HID + lane * 4] = acc;
}

// ---------------- GEMM2: h2 = a1[100000,128] @ W2[128,32], warp per row ----------------
__global__ void k_gemm2(const float* __restrict__ W2) {
    __shared__ float Ws[HID][CLS];
    __shared__ float rowbuf[8][HID];
    int tid = threadIdx.x, lane = tid & 31, wid = tid >> 5;
    for (int i = tid; i < (HID * CLS) / 4; i += 256)
        ((float4*)Ws)[i] = ((const float4*)W2)[i];
    __syncthreads();
    int row = blockIdx.x * 8 + wid;
    if (row >= N_NODES) return;
    float4 v = *(const float4*)&g_a1[(size_t)row * HID + lane * 4];
    *(float4*)&rowbuf[wid][lane * 4] = v;
    __syncwarp();
    float acc = 0.f;
    #pragma unroll 8
    for (int k = 0; k < HID; k++)
        acc = fmaf(rowbuf[wid][k], Ws[k][lane], acc);
    g_h2[(size_t)row * CLS + lane] = acc;
}

// ---------------- agg2 + bias + log_softmax, warp per node (32 classes = 32 lanes) ----------------
__global__ void k_agg2(const float* __restrict__ b2, float* __restrict__ out) {
    int w = (blockIdx.x * blockDim.x + threadIdx.x) >> 5;
    int lane = threadIdx.x & 31;
    if (w >= N_NODES) return;
    int s0 = g_rowptr[w], s1 = g_rowptr[w + 1];
    float dd = g_dinv[w];
    float acc = 0.f;
    for (int e = s0; e < s1; e++) {
        int s = g_csrc[e];
        float nrm = g_dinv[s] * dd;
        acc = fmaf(nrm, g_h2[(size_t)s * CLS + lane], acc);
    }
    acc += b2[lane];
    float m = acc;
    #pragma unroll
    for (int off = 16; off; off >>= 1)
        m = fmaxf(m, __shfl_xor_sync(0xffffffffu, m, off));
    float ex = __expf(acc - m);
    float ssum = ex;
    #pragma unroll
    for (int off = 16; off; off >>= 1)
        ssum += __shfl_xor_sync(0xffffffffu, ssum, off);
    out[(size_t)w * CLS + lane] = acc - m - logf(ssum);
}

extern "C" void kernel_launch(void* const* d_in, const int* in_sizes, int n_in,
                              void* d_out, int out_size) {
    const float* x  = (const float*)d_in[0];
    const float* W1 = (const float*)d_in[1];
    const float* b1 = (const float*)d_in[2];
    const float* W2 = (const float*)d_in[3];
    const float* b2 = (const float*)d_in[4];
    const int*   ei = (const int*)d_in[5];
    float* out = (float*)d_out;

    k_zero_deg<<<(N_NODES + 255) / 256, 256>>>();
    k_count<<<(N_EDGES + 255) / 256, 256>>>(ei);
    k_scan<<<1, 1024>>>();
    k_fill<<<(N_EDGES + 255) / 256, 256>>>(ei);
    k_gemm1<<<(N_NODES + 63) / 64, 256>>>(x, W1);
    k_agg1<<<(N_NODES * 32 + 255) / 256, 256>>>(b1);
    k_gemm2<<<(N_NODES + 7) / 8, 256>>>(W2);
    k_agg2<<<(N_NODES * 32 + 255) / 256, 256>>>(b2, out);
}

// round 3
// speedup vs baseline: 1.8460x; 1.8460x over previous
#include <cuda_runtime.h>
#include <cstdint>

#define N_NODES 100000
#define F_IN    256
#define HID     128
#define CLS     32
#define N_EDGES 1600000
#define NBLK    ((N_NODES + 1023) / 1024)

// ---- device scratch ----
__device__ __align__(16) float g_h1[N_NODES * HID];
__device__ __align__(16) float g_h2[N_NODES * CLS];
__device__ int   g_deg[N_NODES];
__device__ float g_dinv[N_NODES];
__device__ int   g_rowptr[N_NODES + 1];
__device__ int   g_cursor[N_NODES];
__device__ int   g_csrc[N_EDGES];
__device__ int   g_bsum[NBLK];
__device__ int   g_boff[NBLK];

// ---------------- graph preprocessing ----------------
__global__ void k_zero_deg() {
    int i = blockIdx.x * blockDim.x + threadIdx.x;
    if (i < N_NODES) g_deg[i] = 0;
}

__global__ void k_count(const int* __restrict__ ei) {
    int i = blockIdx.x * blockDim.x + threadIdx.x;
    if (i < N_EDGES) atomicAdd(&g_deg[ei[N_EDGES + i]], 1);
}

// per-block scan of deg -> local exclusive in g_rowptr, block total in g_bsum
__global__ void k_blockscan() {
    __shared__ int wsum[32];
    int tid = threadIdx.x, lane = tid & 31, wd = tid >> 5;
    int i = blockIdx.x * 1024 + tid;
    int v = (i < N_NODES) ? g_deg[i] : 0;
    int x = v;
    #pragma unroll
    for (int off = 1; off < 32; off <<= 1) {
        int t = __shfl_up_sync(0xffffffffu, x, off);
        if (lane >= off) x += t;
    }
    if (lane == 31) wsum[wd] = x;
    __syncthreads();
    if (wd == 0) {
        int y = wsum[lane];
        #pragma unroll
        for (int off = 1; off < 32; off <<= 1) {
            int t = __shfl_up_sync(0xffffffffu, y, off);
            if (lane >= off) y += t;
        }
        wsum[lane] = y;
    }
    __syncthreads();
    int excl = x - v + (wd ? wsum[wd - 1] : 0);
    if (i < N_NODES) g_rowptr[i] = excl;
    if (tid == 1023) g_bsum[blockIdx.x] = excl + v;
}

// scan the 98 block sums
__global__ void k_scan2() {
    __shared__ int s[128];
    int tid = threadIdx.x;
    int v = (tid < NBLK) ? g_bsum[tid] : 0;
    s[tid] = v;
    __syncthreads();
    #pragma unroll
    for (int off = 1; off < 128; off <<= 1) {
        int t = (tid >= off) ? s[tid - off] : 0;
        __syncthreads();
        s[tid] += t;
        __syncthreads();
    }
    if (tid < NBLK) g_boff[tid] = s[tid] - v;
    if (tid == NBLK - 1) g_rowptr[N_NODES] = s[tid];
}

__global__ void k_apply() {
    int i = blockIdx.x * blockDim.x + threadIdx.x;
    if (i < N_NODES) {
        int e = g_rowptr[i] + g_boff[i >> 10];
        g_rowptr[i] = e;
        g_cursor[i] = e;
        int d = g_deg[i];
        g_dinv[i] = (d > 0) ? rsqrtf((float)d) : 0.0f;
    }
}

__global__ void k_fill(const int* __restrict__ ei) {
    int i = blockIdx.x * blockDim.x + threadIdx.x;
    if (i < N_EDGES) {
        int s = ei[i];
        int d = ei[N_EDGES + i];
        int p = atomicAdd(&g_cursor[d], 1);
        g_csrc[p] = s;
    }
}

// ---------------- tf32 MMA helpers ----------------
__device__ __forceinline__ uint32_t f2tf(float f) {
    uint32_t r;
    asm("cvt.rna.tf32.f32 %0, %1;" : "=r"(r) : "f"(f));
    return r;
}
__device__ __forceinline__ void mma8(float* c, const uint32_t* a, const uint32_t* b) {
    asm volatile("mma.sync.aligned.m16n8k8.row.col.f32.tf32.tf32.f32 "
        "{%0,%1,%2,%3}, {%4,%5,%6,%7}, {%8,%9}, {%0,%1,%2,%3};"
        : "+f"(c[0]), "+f"(c[1]), "+f"(c[2]), "+f"(c[3])
        : "r"(a[0]), "r"(a[1]), "r"(a[2]), "r"(a[3]), "r"(b[0]), "r"(b[1]));
}

// ---------------- GEMM1: h1 = X @ W1, tf32 tensor cores ----------------
// Block tile 128x128, BK=32, 256 threads = 8 warps (4m x 2n), warp tile 32x64.
#define BM 128
#define BK 32
__global__ __launch_bounds__(256) void k_gemm1(const float* __restrict__ X,
                                               const float* __restrict__ W) {
    __shared__ float As[BM][BK + 4];    // stride 36: conflict-free frag reads
    __shared__ float Bs[BK][HID + 8];   // stride 136
    int tid = threadIdx.x;
    int wid = tid >> 5, lane = tid & 31;
    int gID = lane >> 2, tig = lane & 3;
    int rowBase = (wid >> 1) * 32;
    int colBase = (wid & 1) * 64;
    int row0 = blockIdx.x * BM;

    float c[2][8][4];
    #pragma unroll
    for (int mt = 0; mt < 2; mt++)
        #pragma unroll
        for (int nt = 0; nt < 8; nt++)
            #pragma unroll
            for (int j = 0; j < 4; j++) c[mt][nt][j] = 0.0f;

    for (int k0 = 0; k0 < F_IN; k0 += BK) {
        #pragma unroll
        for (int l = 0; l < 4; l++) {
            int idx = tid + l * 256;              // 0..1023
            int r = idx >> 3, c4 = idx & 7;
            int gr = row0 + r;
            float4 v = make_float4(0.f, 0.f, 0.f, 0.f);
            if (gr < N_NODES)
                v = *(const float4*)&X[(size_t)gr * F_IN + k0 + c4 * 4];
            *(float4*)&As[r][c4 * 4] = v;
        }
        #pragma unroll
        for (int l = 0; l < 4; l++) {
            int idx = tid + l * 256;              // 0..1023
            int r = idx >> 5, c4 = idx & 31;
            *(float4*)&Bs[r][c4 * 4] = *(const float4*)&W[(k0 + r) * HID + c4 * 4];
        }
        __syncthreads();
        #pragma unroll
        for (int kk = 0; kk < BK; kk += 8) {
            uint32_t a[2][4], b[8][2];
            #pragma unroll
            for (int mt = 0; mt < 2; mt++) {
                int r = rowBase + mt * 16 + gID;
                a[mt][0] = f2tf(As[r][kk + tig]);
                a[mt][1] = f2tf(As[r + 8][kk + tig]);
                a[mt][2] = f2tf(As[r][kk + tig + 4]);
                a[mt][3] = f2tf(As[r + 8][kk + tig + 4]);
            }
            #pragma unroll
            for (int nt = 0; nt < 8; nt++) {
                int cc = colBase + nt * 8 + gID;
                b[nt][0] = f2tf(Bs[kk + tig][cc]);
                b[nt][1] = f2tf(Bs[kk + tig + 4][cc]);
            }
            #pragma unroll
            for (int mt = 0; mt < 2; mt++)
                #pragma unroll
                for (int nt = 0; nt < 8; nt++)
                    mma8(c[mt][nt], a[mt], b[nt]);
        }
        __syncthreads();
    }
    #pragma unroll
    for (int mt = 0; mt < 2; mt++) {
        #pragma unroll
        for (int nt = 0; nt < 8; nt++) {
            int gr = row0 + rowBase + mt * 16 + gID;
            int cc = colBase + nt * 8 + 2 * tig;
            if (gr < N_NODES)
                *(float2*)&g_h1[(size_t)gr * HID + cc] = make_float2(c[mt][nt][0], c[mt][nt][1]);
            if (gr + 8 < N_NODES)
                *(float2*)&g_h1[(size_t)(gr + 8) * HID + cc] = make_float2(c[mt][nt][2], c[mt][nt][3]);
        }
    }
}

// ---------------- fused agg1 + relu + GEMM2: h2 = relu(agg(h1)+b1) @ W2 ----------------
__global__ __launch_bounds__(256) void k_agg1f(const float* __restrict__ b1,
                                               const float* __restrict__ W2) {
    __shared__ float Ws[HID][CLS + 1];
    __shared__ float rowbuf[8][HID + 4];
    int tid = threadIdx.x, lane = tid & 31, wid = tid >> 5;
    #pragma unroll
    for (int l = 0; l < 16; l++) {
        int i = tid + l * 256;                    // 0..4095
        Ws[i >> 5][i & 31] = W2[i];
    }
    __syncthreads();

    int w = blockIdx.x * 8 + wid;
    float4 acc = make_float4(0.f, 0.f, 0.f, 0.f);
    if (w < N_NODES) {
        int s0 = g_rowptr[w], s1 = g_rowptr[w + 1];
        float dd = g_dinv[w];
        for (int e = s0; e < s1; e++) {
            int s = g_csrc[e];
            float nrm = g_dinv[s] * dd;
            float4 v = *(const float4*)&g_h1[(size_t)s * HID + lane * 4];
            acc.x = fmaf(nrm, v.x, acc.x);
            acc.y = fmaf(nrm, v.y, acc.y);
            acc.z = fmaf(nrm, v.z, acc.z);
            acc.w = fmaf(nrm, v.w, acc.w);
        }
        float4 bb = *(const float4*)&b1[lane * 4];
        acc.x = fmaxf(acc.x + bb.x, 0.f);
        acc.y = fmaxf(acc.y + bb.y, 0.f);
        acc.z = fmaxf(acc.z + bb.z, 0.f);
        acc.w = fmaxf(acc.w + bb.w, 0.f);
    }
    *(float4*)&rowbuf[wid][lane * 4] = acc;
    __syncwarp();
    if (w < N_NODES) {
        float s = 0.f;
        #pragma unroll
        for (int k = 0; k < HID; k += 4) {
            float4 rv = *(float4*)&rowbuf[wid][k];
            s = fmaf(rv.x, Ws[k + 0][lane], s);
            s = fmaf(rv.y, Ws[k + 1][lane], s);
            s = fmaf(rv.z, Ws[k + 2][lane], s);
            s = fmaf(rv.w, Ws[k + 3][lane], s);
        }
        g_h2[(size_t)w * CLS + lane] = s;
    }
}

// ---------------- agg2 + bias + log_softmax ----------------
__global__ void k_agg2(const float* __restrict__ b2, float* __restrict__ out) {
    int w = (blockIdx.x * blockDim.x + threadIdx.x) >> 5;
    int lane = threadIdx.x & 31;
    if (w >= N_NODES) return;
    int s0 = g_rowptr[w], s1 = g_rowptr[w + 1];
    float dd = g_dinv[w];
    float acc = 0.f;
    for (int e = s0; e < s1; e++) {
        int s = g_csrc[e];
        float nrm = g_dinv[s] * dd;
        acc = fmaf(nrm, g_h2[(size_t)s * CLS + lane], acc);
    }
    acc += b2[lane];
    float m = acc;
    #pragma unroll
    for (int off = 16; off; off >>= 1)
        m = fmaxf(m, __shfl_xor_sync(0xffffffffu, m, off));
    float ex = __expf(acc - m);
    float ssum = ex;
    #pragma unroll
    for (int off = 16; off; off >>= 1)
        ssum += __shfl_xor_sync(0xffffffffu, ssum, off);
    out[(size_t)w * CLS + lane] = acc - m - logf(ssum);
}

extern "C" void kernel_launch(void* const* d_in, const int* in_sizes, int n_in,
                              void* d_out, int out_size) {
    const float* x  = (const float*)d_in[0];
    const float* W1 = (const float*)d_in[1];
    const float* b1 = (const float*)d_in[2];
    const float* W2 = (const float*)d_in[3];
    const float* b2 = (const float*)d_in[4];
    const int*   ei = (const int*)d_in[5];
    float* out = (float*)d_out;

    k_zero_deg<<<(N_NODES + 255) / 256, 256>>>();
    k_count<<<(N_EDGES + 255) / 256, 256>>>(ei);
    k_blockscan<<<NBLK, 1024>>>();
    k_scan2<<<1, 128>>>();
    k_apply<<<(N_NODES + 255) / 256, 256>>>();
    k_fill<<<(N_EDGES + 255) / 256, 256>>>(ei);
    k_gemm1<<<(N_NODES + BM - 1) / BM, 256>>>(x, W1);
    k_agg1f<<<(N_NODES + 7) / 8, 256>>>(b1, W2);
    k_agg2<<<(N_NODES * 32 + 255) / 256, 256>>>(b2, out);
}

// round 4
// speedup vs baseline: 2.0505x; 1.1108x over previous
#include <cuda_runtime.h>
#include <cuda_bf16.h>
#include <cstdint>

#define N_NODES 100000
#define F_IN    256
#define HID     128
#define CLS     32
#define N_EDGES 1600000
#define NBLK    ((N_NODES + 1023) / 1024)

// ---- device scratch ----
__device__ __align__(16) __nv_bfloat16 g_h1b[N_NODES * HID]; // (X@W1) * dinv[row], bf16
__device__ __align__(16) float g_h2[N_NODES * CLS];          // (relu(agg1+b1)@W2) * dinv[row]
__device__ int   g_deg[N_NODES];
__device__ float g_dinv[N_NODES];
__device__ int   g_rowptr[N_NODES + 1];
__device__ int   g_cursor[N_NODES];
__device__ int   g_csrc[N_EDGES];
__device__ int   g_bsum[NBLK];
__device__ int   g_boff[NBLK];

// ---------------- graph preprocessing ----------------
__global__ void k_zero_deg() {
    int i = blockIdx.x * blockDim.x + threadIdx.x;
    if (i < N_NODES) g_deg[i] = 0;
}

__global__ void k_count(const int* __restrict__ ei) {
    int i = blockIdx.x * blockDim.x + threadIdx.x;
    if (i < N_EDGES) atomicAdd(&g_deg[ei[N_EDGES + i]], 1);
}

__global__ void k_blockscan() {
    __shared__ int wsum[32];
    int tid = threadIdx.x, lane = tid & 31, wd = tid >> 5;
    int i = blockIdx.x * 1024 + tid;
    int v = (i < N_NODES) ? g_deg[i] : 0;
    int x = v;
    #pragma unroll
    for (int off = 1; off < 32; off <<= 1) {
        int t = __shfl_up_sync(0xffffffffu, x, off);
        if (lane >= off) x += t;
    }
    if (lane == 31) wsum[wd] = x;
    __syncthreads();
    if (wd == 0) {
        int y = wsum[lane];
        #pragma unroll
        for (int off = 1; off < 32; off <<= 1) {
            int t = __shfl_up_sync(0xffffffffu, y, off);
            if (lane >= off) y += t;
        }
        wsum[lane] = y;
    }
    __syncthreads();
    int excl = x - v + (wd ? wsum[wd - 1] : 0);
    if (i < N_NODES) g_rowptr[i] = excl;
    if (tid == 1023) g_bsum[blockIdx.x] = excl + v;
}

__global__ void k_scan2() {
    __shared__ int s[128];
    int tid = threadIdx.x;
    int v = (tid < NBLK) ? g_bsum[tid] : 0;
    s[tid] = v;
    __syncthreads();
    #pragma unroll
    for (int off = 1; off < 128; off <<= 1) {
        int t = (tid >= off) ? s[tid - off] : 0;
        __syncthreads();
        s[tid] += t;
        __syncthreads();
    }
    if (tid < NBLK) g_boff[tid] = s[tid] - v;
    if (tid == NBLK - 1) g_rowptr[N_NODES] = s[tid];
}

__global__ void k_apply() {
    int i = blockIdx.x * blockDim.x + threadIdx.x;
    if (i < N_NODES) {
        int e = g_rowptr[i] + g_boff[i >> 10];
        g_rowptr[i] = e;
        g_cursor[i] = e;
        int d = g_deg[i];
        g_dinv[i] = (d > 0) ? rsqrtf((float)d) : 0.0f;
    }
}

__global__ void k_fill(const int* __restrict__ ei) {
    int i = blockIdx.x * blockDim.x + threadIdx.x;
    if (i < N_EDGES) {
        int s = ei[i];
        int d = ei[N_EDGES + i];
        int p = atomicAdd(&g_cursor[d], 1);
        g_csrc[p] = s;
    }
}

// ---------------- tf32 MMA helpers ----------------
__device__ __forceinline__ uint32_t f2tf(float f) {
    uint32_t r;
    asm("cvt.rna.tf32.f32 %0, %1;" : "=r"(r) : "f"(f));
    return r;
}
__device__ __forceinline__ void mma8(float* c, const uint32_t* a, const uint32_t* b) {
    asm volatile("mma.sync.aligned.m16n8k8.row.col.f32.tf32.tf32.f32 "
        "{%0,%1,%2,%3}, {%4,%5,%6,%7}, {%8,%9}, {%0,%1,%2,%3};"
        : "+f"(c[0]), "+f"(c[1]), "+f"(c[2]), "+f"(c[3])
        : "r"(a[0]), "r"(a[1]), "r"(a[2]), "r"(a[3]), "r"(b[0]), "r"(b[1]));
}

// ---------------- GEMM1: h1b = (X @ W1) * dinv[row], bf16 out ----------------
// Block tile 128x128, BK=32, 256 threads = 8 warps (4m x 2n), warp tile 32x64.
// tf32 conversion happens at smem-store time.
#define BM 128
#define BK 32
__global__ __launch_bounds__(256) void k_gemm1(const float* __restrict__ X,
                                               const float* __restrict__ W) {
    __shared__ uint32_t As[BM][BK + 4];    // 36: conflict-free
    __shared__ uint32_t Bs[BK][HID + 8];   // 136
    int tid = threadIdx.x;
    int wid = tid >> 5, lane = tid & 31;
    int gID = lane >> 2, tig = lane & 3;
    int rowBase = (wid >> 1) * 32;
    int colBase = (wid & 1) * 64;
    int row0 = blockIdx.x * BM;

    float c[2][8][4];
    #pragma unroll
    for (int mt = 0; mt < 2; mt++)
        #pragma unroll
        for (int nt = 0; nt < 8; nt++)
            #pragma unroll
            for (int j = 0; j < 4; j++) c[mt][nt][j] = 0.0f;

    for (int k0 = 0; k0 < F_IN; k0 += BK) {
        #pragma unroll
        for (int l = 0; l < 4; l++) {
            int idx = tid + l * 256;              // 0..1023
            int r = idx >> 3, c4 = idx & 7;
            int gr = row0 + r;
            float4 v = make_float4(0.f, 0.f, 0.f, 0.f);
            if (gr < N_NODES)
                v = *(const float4*)&X[(size_t)gr * F_IN + k0 + c4 * 4];
            uint32_t* p = &As[r][c4 * 4];
            p[0] = f2tf(v.x); p[1] = f2tf(v.y); p[2] = f2tf(v.z); p[3] = f2tf(v.w);
        }
        #pragma unroll
        for (int l = 0; l < 4; l++) {
            int idx = tid + l * 256;              // 0..1023
            int r = idx >> 5, c4 = idx & 31;
            float4 v = *(const float4*)&W[(k0 + r) * HID + c4 * 4];
            uint32_t* p = &Bs[r][c4 * 4];
            p[0] = f2tf(v.x); p[1] = f2tf(v.y); p[2] = f2tf(v.z); p[3] = f2tf(v.w);
        }
        __syncthreads();
        #pragma unroll
        for (int kk = 0; kk < BK; kk += 8) {
            uint32_t a[2][4], b[8][2];
            #pragma unroll
            for (int mt = 0; mt < 2; mt++) {
                int r = rowBase + mt * 16 + gID;
                a[mt][0] = As[r][kk + tig];
                a[mt][1] = As[r + 8][kk + tig];
                a[mt][2] = As[r][kk + tig + 4];
                a[mt][3] = As[r + 8][kk + tig + 4];
            }
            #pragma unroll
            for (int nt = 0; nt < 8; nt++) {
                int cc = colBase + nt * 8 + gID;
                b[nt][0] = Bs[kk + tig][cc];
                b[nt][1] = Bs[kk + tig + 4][cc];
            }
            #pragma unroll
            for (int mt = 0; mt < 2; mt++)
                #pragma unroll
                for (int nt = 0; nt < 8; nt++)
                    mma8(c[mt][nt], a[mt], b[nt]);
        }
        __syncthreads();
    }
    // epilogue: scale by dinv[row], store bf16
    #pragma unroll
    for (int mt = 0; mt < 2; mt++) {
        int gr0 = row0 + rowBase + mt * 16 + gID;
        float d0 = (gr0 < N_NODES) ? g_dinv[gr0] : 0.f;
        float d1 = (gr0 + 8 < N_NODES) ? g_dinv[gr0 + 8] : 0.f;
        #pragma unroll
        for (int nt = 0; nt < 8; nt++) {
            int cc = colBase + nt * 8 + 2 * tig;
            if (gr0 < N_NODES) {
                __nv_bfloat162 v = __floats2bfloat162_rn(c[mt][nt][0] * d0, c[mt][nt][1] * d0);
                *(__nv_bfloat162*)&g_h1b[(size_t)gr0 * HID + cc] = v;
            }
            if (gr0 + 8 < N_NODES) {
                __nv_bfloat162 v = __floats2bfloat162_rn(c[mt][nt][2] * d1, c[mt][nt][3] * d1);
                *(__nv_bfloat162*)&g_h1b[(size_t)(gr0 + 8) * HID + cc] = v;
            }
        }
    }
}

// ---- fused agg1 + relu + GEMM2, pre-scaled: h2 = (relu(dinv[w]*sum + b1) @ W2) * dinv[w] ----
__global__ __launch_bounds__(256) void k_agg1f(const float* __restrict__ b1,
                                               const float* __restrict__ W2) {
    __shared__ float Ws[HID][CLS + 1];
    __shared__ float rowbuf[8][HID + 4];
    int tid = threadIdx.x, lane = tid & 31, wid = tid >> 5;
    #pragma unroll
    for (int l = 0; l < 16; l++) {
        int i = tid + l * 256;                    // 0..4095
        Ws[i >> 5][i & 31] = W2[i];
    }
    __syncthreads();

    int w = blockIdx.x * 8 + wid;
    float4 acc = make_float4(0.f, 0.f, 0.f, 0.f);
    float dd = 0.f;
    if (w < N_NODES) {
        int s0 = g_rowptr[w], s1 = g_rowptr[w + 1];
        dd = g_dinv[w];
        const uint2* h1v = (const uint2*)g_h1b;   // 4 bf16 per uint2, 32 uint2 per row
        #pragma unroll 4
        for (int e = s0; e < s1; e++) {
            int s = g_csrc[e];
            uint2 u = h1v[(size_t)s * 32 + lane];
            float2 lo = __bfloat1622float2(*(__nv_bfloat162*)&u.x);
            float2 hi = __bfloat1622float2(*(__nv_bfloat162*)&u.y);
            acc.x += lo.x; acc.y += lo.y; acc.z += hi.x; acc.w += hi.y;
        }
        float4 bb = *(const float4*)&b1[lane * 4];
        acc.x = fmaxf(fmaf(acc.x, dd, bb.x), 0.f);
        acc.y = fmaxf(fmaf(acc.y, dd, bb.y), 0.f);
        acc.z = fmaxf(fmaf(acc.z, dd, bb.z), 0.f);
        acc.w = fmaxf(fmaf(acc.w, dd, bb.w), 0.f);
    }
    *(float4*)&rowbuf[wid][lane * 4] = acc;
    __syncwarp();
    if (w < N_NODES) {
        float s = 0.f;
        #pragma unroll
        for (int k = 0; k < HID; k += 4) {
            float4 rv = *(float4*)&rowbuf[wid][k];
            s = fmaf(rv.x, Ws[k + 0][lane], s);
            s = fmaf(rv.y, Ws[k + 1][lane], s);
            s = fmaf(rv.z, Ws[k + 2][lane], s);
            s = fmaf(rv.w, Ws[k + 3][lane], s);
        }
        g_h2[(size_t)w * CLS + lane] = s * dd;    // pre-scale by dinv[w]
    }
}

// ---------------- agg2 + bias + log_softmax ----------------
__global__ void k_agg2(const float* __restrict__ b2, float* __restrict__ out) {
    int w = (blockIdx.x * blockDim.x + threadIdx.x) >> 5;
    int lane = threadIdx.x & 31;
    if (w >= N_NODES) return;
    int s0 = g_rowptr[w], s1 = g_rowptr[w + 1];
    float dd = g_dinv[w];
    float acc = 0.f;
    #pragma unroll 4
    for (int e = s0; e < s1; e++) {
        int s = g_csrc[e];
        acc += g_h2[(size_t)s * CLS + lane];
    }
    acc = fmaf(acc, dd, b2[lane]);
    float m = acc;
    #pragma unroll
    for (int off = 16; off; off >>= 1)
        m = fmaxf(m, __shfl_xor_sync(0xffffffffu, m, off));
    float ex = __expf(acc - m);
    float ssum = ex;
    #pragma unroll
    for (int off = 16; off; off >>= 1)
        ssum += __shfl_xor_sync(0xffffffffu, ssum, off);
    out[(size_t)w * CLS + lane] = acc - m - logf(ssum);
}

extern "C" void kernel_launch(void* const* d_in, const int* in_sizes, int n_in,
                              void* d_out, int out_size) {
    const float* x  = (const float*)d_in[0];
    const float* W1 = (const float*)d_in[1];
    const float* b1 = (const float*)d_in[2];
    const float* W2 = (const float*)d_in[3];
    const float* b2 = (const float*)d_in[4];
    const int*   ei = (const int*)d_in[5];
    float* out = (float*)d_out;

    k_zero_deg<<<(N_NODES + 255) / 256, 256>>>();
    k_count<<<(N_EDGES + 255) / 256, 256>>>(ei);
    k_blockscan<<<NBLK, 1024>>>();
    k_scan2<<<1, 128>>>();
    k_apply<<<(N_NODES + 255) / 256, 256>>>();
    k_fill<<<(N_EDGES + 255) / 256, 256>>>(ei);
    k_gemm1<<<(N_NODES + BM - 1) / BM, 256>>>(x, W1);
    k_agg1f<<<(N_NODES + 7) / 8, 256>>>(b1, W2);
    k_agg2<<<(N_NODES * 32 + 255) / 256, 256>>>(b2, out);
}

// round 5
// speedup vs baseline: 2.1015x; 1.0249x over previous
#include <cuda_runtime.h>
#include <cuda_bf16.h>
#include <cuda_fp16.h>
#include <cstdint>

#define N_NODES 100000
#define F_IN    256
#define HID     128
#define CLS     32
#define N_EDGES 1600000
#define NBLK    ((N_NODES + 1023) / 1024)

// ---- device scratch ----
__device__ __align__(16) __nv_bfloat16 g_h1b[N_NODES * HID]; // X@W1 (unscaled), bf16
__device__ __align__(16) __half g_h2h[N_NODES * CLS];        // (relu(...)@W2) * dinv[row], fp16
__device__ int   g_deg[N_NODES];
__device__ float g_dinv[N_NODES];
__device__ int   g_rowptr[N_NODES + 1];
__device__ int   g_cursor[N_NODES];
__device__ int   g_csrc[N_EDGES];
__device__ int   g_bsum[NBLK];
__device__ int   g_boff[NBLK];

// ---------------- graph preprocessing ----------------
__global__ void k_zero_deg() {
    int i = blockIdx.x * blockDim.x + threadIdx.x;
    if (i < N_NODES) g_deg[i] = 0;
}

__global__ void k_count(const int* __restrict__ ei) {
    int i = blockIdx.x * blockDim.x + threadIdx.x;          // i indexes groups of 4
    int base = i * 4;
    if (base + 3 < N_EDGES) {
        int4 d = *(const int4*)&ei[N_EDGES + base];
        atomicAdd(&g_deg[d.x], 1);
        atomicAdd(&g_deg[d.y], 1);
        atomicAdd(&g_deg[d.z], 1);
        atomicAdd(&g_deg[d.w], 1);
    } else {
        for (int e = base; e < N_EDGES; e++) atomicAdd(&g_deg[ei[N_EDGES + e]], 1);
    }
}

__global__ void k_blockscan() {
    __shared__ int wsum[32];
    int tid = threadIdx.x, lane = tid & 31, wd = tid >> 5;
    int i = blockIdx.x * 1024 + tid;
    int v = (i < N_NODES) ? g_deg[i] : 0;
    int x = v;
    #pragma unroll
    for (int off = 1; off < 32; off <<= 1) {
        int t = __shfl_up_sync(0xffffffffu, x, off);
        if (lane >= off) x += t;
    }
    if (lane == 31) wsum[wd] = x;
    __syncthreads();
    if (wd == 0) {
        int y = wsum[lane];
        #pragma unroll
        for (int off = 1; off < 32; off <<= 1) {
            int t = __shfl_up_sync(0xffffffffu, y, off);
            if (lane >= off) y += t;
        }
        wsum[lane] = y;
    }
    __syncthreads();
    int excl = x - v + (wd ? wsum[wd - 1] : 0);
    if (i < N_NODES) g_rowptr[i] = excl;
    if (tid == 1023) g_bsum[blockIdx.x] = excl + v;
}

__global__ void k_scan2() {
    __shared__ int s[128];
    int tid = threadIdx.x;
    int v = (tid < NBLK) ? g_bsum[tid] : 0;
    s[tid] = v;
    __syncthreads();
    #pragma unroll
    for (int off = 1; off < 128; off <<= 1) {
        int t = (tid >= off) ? s[tid - off] : 0;
        __syncthreads();
        s[tid] += t;
        __syncthreads();
    }
    if (tid < NBLK) g_boff[tid] = s[tid] - v;
    if (tid == NBLK - 1) g_rowptr[N_NODES] = s[tid];
}

__global__ void k_apply() {
    int i = blockIdx.x * blockDim.x + threadIdx.x;
    if (i < N_NODES) {
        int e = g_rowptr[i] + g_boff[i >> 10];
        g_rowptr[i] = e;
        g_cursor[i] = e;
        int d = g_deg[i];
        g_dinv[i] = (d > 0) ? rsqrtf((float)d) : 0.0f;
    }
}

__global__ void k_fill(const int* __restrict__ ei) {
    int i = blockIdx.x * blockDim.x + threadIdx.x;
    if (i < N_EDGES) {
        int s = ei[i];
        int d = ei[N_EDGES + i];
        int p = atomicAdd(&g_cursor[d], 1);
        g_csrc[p] = s;
    }
}

// ---------------- tf32 MMA helpers ----------------
__device__ __forceinline__ uint32_t f2tf(float f) {
    uint32_t r;
    asm("cvt.rna.tf32.f32 %0, %1;" : "=r"(r) : "f"(f));
    return r;
}
__device__ __forceinline__ void mma8(float* c, const uint32_t* a, const uint32_t* b) {
    asm volatile("mma.sync.aligned.m16n8k8.row.col.f32.tf32.tf32.f32 "
        "{%0,%1,%2,%3}, {%4,%5,%6,%7}, {%8,%9}, {%0,%1,%2,%3};"
        : "+f"(c[0]), "+f"(c[1]), "+f"(c[2]), "+f"(c[3])
        : "r"(a[0]), "r"(a[1]), "r"(a[2]), "r"(a[3]), "r"(b[0]), "r"(b[1]));
}

// ---------------- GEMM1: h1b = X @ W1 (unscaled), bf16 out ----------------
#define BM 128
#define BK 32
__global__ __launch_bounds__(256) void k_gemm1(const float* __restrict__ X,
                                               const float* __restrict__ W) {
    __shared__ uint32_t As[BM][BK + 4];
    __shared__ uint32_t Bs[BK][HID + 8];
    int tid = threadIdx.x;
    int wid = tid >> 5, lane = tid & 31;
    int gID = lane >> 2, tig = lane & 3;
    int rowBase = (wid >> 1) * 32;
    int colBase = (wid & 1) * 64;
    int row0 = blockIdx.x * BM;

    float c[2][8][4];
    #pragma unroll
    for (int mt = 0; mt < 2; mt++)
        #pragma unroll
        for (int nt = 0; nt < 8; nt++)
            #pragma unroll
            for (int j = 0; j < 4; j++) c[mt][nt][j] = 0.0f;

    for (int k0 = 0; k0 < F_IN; k0 += BK) {
        #pragma unroll
        for (int l = 0; l < 4; l++) {
            int idx = tid + l * 256;
            int r = idx >> 3, c4 = idx & 7;
            int gr = row0 + r;
            float4 v = make_float4(0.f, 0.f, 0.f, 0.f);
            if (gr < N_NODES)
                v = *(const float4*)&X[(size_t)gr * F_IN + k0 + c4 * 4];
            uint32_t* p = &As[r][c4 * 4];
            p[0] = f2tf(v.x); p[1] = f2tf(v.y); p[2] = f2tf(v.z); p[3] = f2tf(v.w);
        }
        #pragma unroll
        for (int l = 0; l < 4; l++) {
            int idx = tid + l * 256;
            int r = idx >> 5, c4 = idx & 31;
            float4 v = *(const float4*)&W[(k0 + r) * HID + c4 * 4];
            uint32_t* p = &Bs[r][c4 * 4];
            p[0] = f2tf(v.x); p[1] = f2tf(v.y); p[2] = f2tf(v.z); p[3] = f2tf(v.w);
        }
        __syncthreads();
        #pragma unroll
        for (int kk = 0; kk < BK; kk += 8) {
            uint32_t a[2][4], b[8][2];
            #pragma unroll
            for (int mt = 0; mt < 2; mt++) {
                int r = rowBase + mt * 16 + gID;
                a[mt][0] = As[r][kk + tig];
                a[mt][1] = As[r + 8][kk + tig];
                a[mt][2] = As[r][kk + tig + 4];
                a[mt][3] = As[r + 8][kk + tig + 4];
            }
            #pragma unroll
            for (int nt = 0; nt < 8; nt++) {
                int cc = colBase + nt * 8 + gID;
                b[nt][0] = Bs[kk + tig][cc];
                b[nt][1] = Bs[kk + tig + 4][cc];
            }
            #pragma unroll
            for (int mt = 0; mt < 2; mt++)
                #pragma unroll
                for (int nt = 0; nt < 8; nt++)
                    mma8(c[mt][nt], a[mt], b[nt]);
        }
        __syncthreads();
    }
    #pragma unroll
    for (int mt = 0; mt < 2; mt++) {
        int gr0 = row0 + rowBase + mt * 16 + gID;
        #pragma unroll
        for (int nt = 0; nt < 8; nt++) {
            int cc = colBase + nt * 8 + 2 * tig;
            if (gr0 < N_NODES)
                *(__nv_bfloat162*)&g_h1b[(size_t)gr0 * HID + cc] =
                    __floats2bfloat162_rn(c[mt][nt][0], c[mt][nt][1]);
            if (gr0 + 8 < N_NODES)
                *(__nv_bfloat162*)&g_h1b[(size_t)(gr0 + 8) * HID + cc] =
                    __floats2bfloat162_rn(c[mt][nt][2], c[mt][nt][3]);
        }
    }
}

// ---- fused agg1 + relu + GEMM2: h2h = (relu(dd*Σ dinv[s]h1[s] + b1) @ W2) * dd ----
__global__ __launch_bounds__(256) void k_agg1f(const float* __restrict__ b1,
                                               const float* __restrict__ W2) {
    __shared__ float Ws[HID][CLS + 1];
    __shared__ float rowbuf[8][HID + 4];
    int tid = threadIdx.x, lane = tid & 31, wid = tid >> 5;
    #pragma unroll
    for (int l = 0; l < 16; l++) {
        int i = tid + l * 256;
        Ws[i >> 5][i & 31] = W2[i];
    }
    __syncthreads();

    int w = blockIdx.x * 8 + wid;
    float4 acc = make_float4(0.f, 0.f, 0.f, 0.f);
    float dd = 0.f;
    if (w < N_NODES) {
        int s0 = g_rowptr[w], s1 = g_rowptr[w + 1];
        dd = g_dinv[w];
        const uint2* h1v = (const uint2*)g_h1b;
        #pragma unroll 4
        for (int e = s0; e < s1; e++) {
            int s = g_csrc[e];
            float nrm = g_dinv[s];
            uint2 u = h1v[(size_t)s * 32 + lane];
            float2 lo = __bfloat1622float2(*(__nv_bfloat162*)&u.x);
            float2 hi = __bfloat1622float2(*(__nv_bfloat162*)&u.y);
            acc.x = fmaf(nrm, lo.x, acc.x);
            acc.y = fmaf(nrm, lo.y, acc.y);
            acc.z = fmaf(nrm, hi.x, acc.z);
            acc.w = fmaf(nrm, hi.y, acc.w);
        }
        float4 bb = *(const float4*)&b1[lane * 4];
        acc.x = fmaxf(fmaf(acc.x, dd, bb.x), 0.f);
        acc.y = fmaxf(fmaf(acc.y, dd, bb.y), 0.f);
        acc.z = fmaxf(fmaf(acc.z, dd, bb.z), 0.f);
        acc.w = fmaxf(fmaf(acc.w, dd, bb.w), 0.f);
    }
    *(float4*)&rowbuf[wid][lane * 4] = acc;
    __syncwarp();
    if (w < N_NODES) {
        float s = 0.f;
        #pragma unroll
        for (int k = 0; k < HID; k += 4) {
            float4 rv = *(float4*)&rowbuf[wid][k];
            s = fmaf(rv.x, Ws[k + 0][lane], s);
            s = fmaf(rv.y, Ws[k + 1][lane], s);
            s = fmaf(rv.z, Ws[k + 2][lane], s);
            s = fmaf(rv.w, Ws[k + 3][lane], s);
        }
        g_h2h[(size_t)w * CLS + lane] = __float2half(s * dd);
    }
}

// ---------------- agg2 + bias + log_softmax ----------------
__global__ void k_agg2(const float* __restrict__ b2, float* __restrict__ out) {
    int w = (blockIdx.x * blockDim.x + threadIdx.x) >> 5;
    int lane = threadIdx.x & 31;
    if (w >= N_NODES) return;
    int s0 = g_rowptr[w], s1 = g_rowptr[w + 1];
    float dd = g_dinv[w];
    float acc = 0.f;
    #pragma unroll 4
    for (int e = s0; e < s1; e++) {
        int s = g_csrc[e];
        acc += __half2float(g_h2h[(size_t)s * CLS + lane]);
    }
    acc = fmaf(acc, dd, b2[lane]);
    float m = acc;
    #pragma unroll
    for (int off = 16; off; off >>= 1)
        m = fmaxf(m, __shfl_xor_sync(0xffffffffu, m, off));
    float ex = __expf(acc - m);
    float ssum = ex;
    #pragma unroll
    for (int off = 16; off; off >>= 1)
        ssum += __shfl_xor_sync(0xffffffffu, ssum, off);
    out[(size_t)w * CLS + lane] = acc - m - logf(ssum);
}

extern "C" void kernel_launch(void* const* d_in, const int* in_sizes, int n_in,
                              void* d_out, int out_size) {
    const float* x  = (const float*)d_in[0];
    const float* W1 = (const float*)d_in[1];
    const float* b1 = (const float*)d_in[2];
    const float* W2 = (const float*)d_in[3];
    const float* b2 = (const float*)d_in[4];
    const int*   ei = (const int*)d_in[5];
    float* out = (float*)d_out;

    static cudaStream_t s2 = nullptr;
    static cudaEvent_t evFork = nullptr, evJoin = nullptr;
    if (!s2) {
        cudaStreamCreateWithFlags(&s2, cudaStreamNonBlocking);
        cudaEventCreateWithFlags(&evFork, cudaEventDisableTiming);
        cudaEventCreateWithFlags(&evJoin, cudaEventDisableTiming);
    }

    // fork: gemm1 (independent of graph preprocessing) on side stream
    cudaEventRecord(evFork, 0);
    cudaStreamWaitEvent(s2, evFork, 0);
    k_gemm1<<<(N_NODES + BM - 1) / BM, 256, 0, s2>>>(x, W1);
    cudaEventRecord(evJoin, s2);

    // preprocessing chain on main stream (overlaps with gemm1)
    k_zero_deg<<<(N_NODES + 255) / 256, 256>>>();
    k_count<<<(N_EDGES / 4 + 255) / 256, 256>>>(ei);
    k_blockscan<<<NBLK, 1024>>>();
    k_scan2<<<1, 128>>>();
    k_apply<<<(N_NODES + 255) / 256, 256>>>();
    k_fill<<<(N_EDGES + 255) / 256, 256>>>(ei);

    // join: agg1f needs both h1 and CSR
    cudaStreamWaitEvent(0, evJoin, 0);
    k_agg1f<<<(N_NODES + 7) / 8, 256>>>(b1, W2);
    k_agg2<<<(N_NODES * 32 + 255) / 256, 256>>>(b2, out);
}